// round 10
// baseline (speedup 1.0000x reference)
#include <cuda_runtime.h>
#include <cuda_bf16.h>
#include <math.h>
#include <stdint.h>

#define TSTEPS  20
#define NLAYERS 4
#define DM      512
#define DS      128
#define ROWS    2048      // BATCH(4) * SEQ(512)
#define VOCAB   32000

// ---------------- scratch (device globals; no allocations allowed) ----------
__device__ uint32_t      g_bits[2][TSTEPS][ROWS][16];
__device__ float         g_AT[NLAYERS][DS * DS];      // AT[j*DS+i] = A[i][j]
__device__ float         g_BT[NLAYERS][DM * DS];      // BT[d*DS+i] = B[i][d]
__device__ float         g_CT[NLAYERS][DS * DM];      // CT[i*DM+d] = C[d][i]
__device__ __nv_bfloat16 g_cntb[ROWS * DM];           // exact integer spike counts
__device__ __nv_bfloat16 g_wph[(size_t)VOCAB * DM];   // bf16 hi of Wp
__device__ __nv_bfloat16 g_wpl[(size_t)VOCAB * DM];   // bf16 lo of Wp

// ---------------- weight transposes ----------------------------------------
__global__ void prep_kernel(const float* __restrict__ A,
                            const float* __restrict__ Bm,
                            const float* __restrict__ Cm) {
    int stride = gridDim.x * blockDim.x;
    int gid = blockIdx.x * blockDim.x + threadIdx.x;
    for (int idx = gid; idx < NLAYERS * DS * DS; idx += stride) {
        int l = idx / (DS * DS); int rm = idx % (DS * DS);
        int i = rm / DS, j = rm % DS;
        g_AT[l][j * DS + i] = A[idx];
    }
    for (int idx = gid; idx < NLAYERS * DS * DM; idx += stride) {
        int l = idx / (DS * DM); int rm = idx % (DS * DM);
        int i = rm / DM, d = rm % DM;
        g_BT[l][d * DS + i] = Bm[idx];
    }
    for (int idx = gid; idx < NLAYERS * DM * DS; idx += stride) {
        int l = idx / (DM * DS); int rm = idx % (DM * DS);
        int d = rm / DS, i = rm % DS;
        g_CT[l][i * DM + d] = Cm[idx];
    }
}

// ---------------- Wp two-term bf16 split ------------------------------------
__global__ void split_wp_kernel(const float* __restrict__ Wp) {
    long long i = (long long)blockIdx.x * blockDim.x + threadIdx.x;
    if (i >= (long long)VOCAB * DM) return;
    float w = Wp[i];
    __nv_bfloat16 h = __float2bfloat16(w);
    g_wph[i] = h;
    g_wpl[i] = __float2bfloat16(w - __bfloat162float(h));
}

__global__ void zero_bits_kernel() {
    int gid = blockIdx.x * blockDim.x + threadIdx.x;
    uint32_t* p = &g_bits[0][0][0][0];
    int n = TSTEPS * ROWS * 16;          // only buffer 0 (encode's atomicOr target)
    for (int i = gid; i < n; i += gridDim.x * blockDim.x) p[i] = 0u;
}

// ---------------- temporal encoding (exact fp32 logistic, as validated) -----
__global__ void encode_kernel(const int* __restrict__ ids,
                              const float* __restrict__ emb) {
    int gid = blockIdx.x * blockDim.x + threadIdx.x;
    if (gid >= ROWS * DM) return;
    int r = gid >> 9, d = gid & (DM - 1);
    float x = emb[(long long)ids[r] * DM + d];
    float sgf = 1.0f / (1.0f + expf(-x));
    int t = (int)floorf(sgf * 19.0f);
    if (t < 0) t = 0;
    if (t > 19) t = 19;
    atomicOr(&g_bits[0][t][r][d >> 5], 1u << (d & 31));
}

// ---------------- LIF-SSM layer: 4 rows per CTA -----------------------------
// Per-row arithmetic identical to the validated kernel (ascending sparse sums,
// single accumulator per dot, separately-rounded A/B dots). 4 rows share the
// CTA so weight rows reused across rows hit L1, and unpack/sync overhead is
// amortized. Threads 0-127 process rows 0,1; threads 128-255 rows 2,3.
// If last!=0, spike counts accumulate in registers and g_cntb is written
// directly (no g_bits writes, no count kernel).
__global__ __launch_bounds__(256) void ssm4_kernel(int layer, int inb, int outb,
                                                   const float* __restrict__ Dfull,
                                                   int last) {
    int tid  = threadIdx.x;
    int half = tid >> 7;          // 0: rows 0,1   1: rows 2,3
    int ltid = tid & 127;         // state/output dim within row
    int lane = tid & 31;
    int wp4  = ltid >> 5;
    int r0   = blockIdx.x * 4;
    int rA   = 2 * half, rB = 2 * half + 1;   // local row indices

    const float* __restrict__ AT = g_AT[layer];
    const float* __restrict__ BT = g_BT[layer];
    const float* __restrict__ CT = g_CT[layer];
    const float* __restrict__ Dv = Dfull + layer * DM;

    __shared__ uint32_t sh_x[4][16];
    __shared__ uint32_t sh_h[4][4];
    __shared__ int sh_xidx[4][512];
    __shared__ int sh_hidx[4][128];
    __shared__ int sh_nx[4], sh_nh[4];

    float v1[2] = {0.f, 0.f};
    float v2[2][4] = {{0.f,0.f,0.f,0.f},{0.f,0.f,0.f,0.f}};
    float cnt[2][4] = {{0.f,0.f,0.f,0.f},{0.f,0.f,0.f,0.f}};
    if (tid < 4) { sh_nh[tid] = 0; sh_nx[tid] = 0; }

    for (int t = 0; t < TSTEPS; t++) {
        __syncthreads();                          // prior iter done with sh_x
        if (tid < 64) sh_x[tid >> 4][tid & 15] = g_bits[inb][t][r0 + (tid >> 4)][tid & 15];
        __syncthreads();

        // unpack x bits -> ascending index lists (4 rows, 16-lane segments)
        if (tid < 64) {
            int rr = tid >> 4, wi = tid & 15;
            uint32_t w = sh_x[rr][wi];
            int c = __popc(w);
            int incl = c;
            #pragma unroll
            for (int off = 1; off < 16; off <<= 1) {
                int y = __shfl_up_sync(0xffffffffu, incl, off);
                if ((lane & 15) >= off) incl += y;
            }
            int pos = incl - c;
            while (w) {
                int b = __ffs(w) - 1; w &= w - 1;
                sh_xidx[rr][pos++] = ((wi << 5) + b) * DS;
            }
            if ((lane & 15) == 15) sh_nx[rr] = incl;
        }
        __syncthreads();

        // ---- state_update for this half's two rows ----
        int nh0 = sh_nh[rA], nh1 = sh_nh[rB];
        int nx0 = sh_nx[rA], nx1 = sh_nx[rB];
        float sa0 = 0.f, sa1 = 0.f;
        #pragma unroll 4
        for (int i = 0; i < nh0; i++) sa0 += AT[sh_hidx[rA][i] * DS + ltid];
        #pragma unroll 4
        for (int i = 0; i < nh1; i++) sa1 += AT[sh_hidx[rB][i] * DS + ltid];
        float sb0 = 0.f, sb1 = 0.f;
        #pragma unroll 4
        for (int i = 0; i < nx0; i++) sb0 += BT[sh_xidx[rA][i] + ltid];
        #pragma unroll 4
        for (int i = 0; i < nx1; i++) sb1 += BT[sh_xidx[rB][i] + ltid];
        float u0 = sa0 + sb0, u1 = sa1 + sb1;

        v1[0] = v1[0] + (u0 - v1[0]) * 0.5f;
        v1[1] = v1[1] + (u1 - v1[1]) * 0.5f;
        int s10 = (v1[0] - 1.0f) >= 0.f;
        int s11 = (v1[1] - 1.0f) >= 0.f;
        uint32_t hb0 = __ballot_sync(0xffffffffu, s10);
        uint32_t hb1 = __ballot_sync(0xffffffffu, s11);
        if (s10) v1[0] = 0.f;
        if (s11) v1[1] = 0.f;
        __syncthreads();                          // old sh_hidx fully consumed
        if (lane == 0) { sh_h[rA][wp4] = hb0; sh_h[rB][wp4] = hb1; }
        __syncthreads();

        // unpack new h bits (4 rows x 4 words = 16 threads, 4-lane segments)
        if (tid < 16) {
            int rr = tid >> 2, wi = tid & 3;
            uint32_t w = sh_h[rr][wi];
            int c = __popc(w);
            int incl = c;
            #pragma unroll
            for (int off = 1; off < 4; off <<= 1) {
                int y = __shfl_up_sync(0xffffu, incl, off);
                if ((lane & 3) >= off) incl += y;
            }
            int pos = incl - c;
            while (w) {
                int b = __ffs(w) - 1; w &= w - 1;
                sh_hidx[rr][pos++] = (wi << 5) + b;
            }
            if ((lane & 3) == 3) sh_nh[rr] = incl;
        }
        __syncthreads();

        // ---- output_update for this half's two rows ----
        #pragma unroll
        for (int j = 0; j < 2; j++) {
            int rr = 2 * half + j;
            int nh2 = sh_nh[rr];
            float sc0 = 0.f, sc1 = 0.f, sc2 = 0.f, sc3 = 0.f;
            #pragma unroll 2
            for (int i = 0; i < nh2; i++) {
                const float* crow = CT + sh_hidx[rr][i] * DM + ltid;
                sc0 += crow[0];
                sc1 += crow[128];
                sc2 += crow[256];
                sc3 += crow[384];
            }
            float sc[4] = {sc0, sc1, sc2, sc3};
            #pragma unroll
            for (int k = 0; k < 4; k++) {
                float u2 = sc[k];
                if ((sh_x[rr][4 * k + wp4] >> lane) & 1u) u2 = u2 + Dv[ltid + 128 * k];
                v2[j][k] = v2[j][k] + (u2 - v2[j][k]) * 0.5f;
                int s2 = (v2[j][k] - 1.0f) >= 0.f;
                if (!last) {
                    uint32_t ob = __ballot_sync(0xffffffffu, s2);
                    if (lane == 0) g_bits[outb][t][r0 + rr][4 * k + wp4] = ob;
                } else {
                    cnt[j][k] += s2 ? 1.0f : 0.0f;
                }
                if (s2) v2[j][k] = 0.f;
            }
        }
    }

    if (last) {
        #pragma unroll
        for (int j = 0; j < 2; j++) {
            int row = r0 + 2 * half + j;
            #pragma unroll
            for (int k = 0; k < 4; k++)
                g_cntb[(size_t)row * DM + ltid + 128 * k] = __float2bfloat16(cnt[j][k]);
        }
    }
}

// ============ logits GEMM: split-bf16 mma.sync + ldmatrix, 3-stage cp.async ==
#define SPAD   40                        // bf16 per smem row (80 B pitch)
#define KC     32                        // K per chunk
#define NCH    (DM / KC)                 // 16 chunks
#define ST     3                         // pipeline stages
#define MAT_B  (128 * SPAD * 2)          // 10240 B per matrix tile
#define STAGE_B (3 * MAT_B)              // A + Bh + Bl
#define GSMEM_BYTES (ST * STAGE_B)       // 92160

__device__ __forceinline__ void mma16816(float* d, const uint32_t* a, const uint32_t* b) {
    asm volatile(
        "mma.sync.aligned.m16n8k16.row.col.f32.bf16.bf16.f32 "
        "{%0,%1,%2,%3}, {%4,%5,%6,%7}, {%8,%9}, {%0,%1,%2,%3};"
        : "+f"(d[0]), "+f"(d[1]), "+f"(d[2]), "+f"(d[3])
        : "r"(a[0]), "r"(a[1]), "r"(a[2]), "r"(a[3]), "r"(b[0]), "r"(b[1]));
}
__device__ __forceinline__ void ldmx4(uint32_t* r, uint32_t a) {
    asm volatile("ldmatrix.sync.aligned.m8n8.x4.shared.b16 {%0,%1,%2,%3}, [%4];"
        : "=r"(r[0]), "=r"(r[1]), "=r"(r[2]), "=r"(r[3]) : "r"(a));
}
__device__ __forceinline__ void ldmx2(uint32_t* r, uint32_t a) {
    asm volatile("ldmatrix.sync.aligned.m8n8.x2.shared.b16 {%0,%1}, [%2];"
        : "=r"(r[0]), "=r"(r[1]) : "r"(a));
}
__device__ __forceinline__ void cpasync16(uint32_t dst, const void* src) {
    asm volatile("cp.async.ca.shared.global [%0], [%1], 16;" :: "r"(dst), "l"(src));
}
__device__ __forceinline__ uint32_t smem_u32(const void* p) {
    uint32_t a;
    asm("{ .reg .u64 t; cvta.to.shared.u64 t, %1; cvt.u32.u64 %0, t; }"
        : "=r"(a) : "l"(p));
    return a;
}

__global__ __launch_bounds__(256, 2) void gemm_bf16_kernel(const float* __restrict__ bp,
                                                           float* __restrict__ out) {
    extern __shared__ char smem[];
    uint32_t sbase = smem_u32(smem);

    int bm = blockIdx.x, bn = blockIdx.y;   // bm fastest -> Wp tile reused in L2
    int tid = threadIdx.x;
    int w   = tid >> 5;
    int wm  = w >> 2, wn = w & 3;           // 2 x 4 warps
    int lane = tid & 31;
    int g = lane >> 2, tig = lane & 3;

    const __nv_bfloat16* asrc = g_cntb + (size_t)(bm * 128) * DM;
    const __nv_bfloat16* hsrc = g_wph  + (size_t)(bn * 128) * DM;
    const __nv_bfloat16* lsrc = g_wpl  + (size_t)(bn * 128) * DM;

    int a_q = lane >> 3, a_r = lane & 7;
    uint32_t a_off = (uint32_t)(((wm * 64 + (a_q & 1) * 8 + a_r) * SPAD +
                                 (a_q >> 1) * 8) * 2);
    int b_r = lane & 7, b_q = (lane >> 3) & 1;
    uint32_t b_off = (uint32_t)(((wn * 32 + b_r) * SPAD + b_q * 8) * 2);

    int crow  = tid >> 1;
    int chalf = (tid & 1) * 32;

    auto issue_stage = [&](int s, int c) {
        uint32_t dbase = sbase + s * STAGE_B + crow * (SPAD * 2) + chalf;
        size_t goff = (size_t)crow * DM + c * KC + (chalf >> 1);
        cpasync16(dbase,                  asrc + goff);
        cpasync16(dbase + 16,             asrc + goff + 8);
        cpasync16(dbase + MAT_B,          hsrc + goff);
        cpasync16(dbase + MAT_B + 16,     hsrc + goff + 8);
        cpasync16(dbase + 2 * MAT_B,      lsrc + goff);
        cpasync16(dbase + 2 * MAT_B + 16, lsrc + goff + 8);
    };

    #pragma unroll
    for (int s = 0; s < ST - 1; s++) {
        issue_stage(s, s);
        asm volatile("cp.async.commit_group;" ::: "memory");
    }

    float acc[4][4][4];
    #pragma unroll
    for (int i = 0; i < 4; i++)
        #pragma unroll
        for (int j = 0; j < 4; j++)
            #pragma unroll
            for (int q = 0; q < 4; q++) acc[i][j][q] = 0.f;

    #pragma unroll 1
    for (int c = 0; c < NCH; c++) {
        if (c < NCH - 1) asm volatile("cp.async.wait_group 1;" ::: "memory");
        else             asm volatile("cp.async.wait_group 0;" ::: "memory");
        __syncthreads();

        if (c + 2 < NCH) {
            issue_stage((c + 2) % ST, c + 2);
            asm volatile("cp.async.commit_group;" ::: "memory");
        }

        uint32_t st = sbase + (c % ST) * STAGE_B;

        #pragma unroll
        for (int ks = 0; ks < KC / 16; ks++) {
            uint32_t kof = (uint32_t)(ks * 16 * 2);
            uint32_t afr[4][4];
            #pragma unroll
            for (int mf = 0; mf < 4; mf++)
                ldmx4(afr[mf], st + a_off + (uint32_t)(mf * 16 * SPAD * 2) + kof);
            #pragma unroll
            for (int nf = 0; nf < 4; nf++) {
                uint32_t bof = b_off + (uint32_t)(nf * 8 * SPAD * 2) + kof;
                uint32_t bh[2], bl[2];
                ldmx2(bh, st + MAT_B + bof);
                ldmx2(bl, st + 2 * MAT_B + bof);
                #pragma unroll
                for (int mf = 0; mf < 4; mf++) {
                    mma16816(acc[mf][nf], afr[mf], bh);
                    mma16816(acc[mf][nf], afr[mf], bl);
                }
            }
        }
        __syncthreads();
    }

    #pragma unroll
    for (int nf = 0; nf < 4; nf++) {
        int col = bn * 128 + wn * 32 + nf * 8 + 2 * tig;
        float2 bias = *(const float2*)(bp + col);
        #pragma unroll
        for (int mf = 0; mf < 4; mf++) {
            int row0 = bm * 128 + wm * 64 + mf * 16 + g;
            float2 o0, o1;
            o0.x = acc[mf][nf][0] * 0.05f + bias.x;
            o0.y = acc[mf][nf][1] * 0.05f + bias.y;
            o1.x = acc[mf][nf][2] * 0.05f + bias.x;
            o1.y = acc[mf][nf][3] * 0.05f + bias.y;
            *(float2*)(out + (size_t)row0 * VOCAB + col)       = o0;
            *(float2*)(out + (size_t)(row0 + 8) * VOCAB + col) = o1;
        }
    }
}

// ---------------- launch -----------------------------------------------------
extern "C" void kernel_launch(void* const* d_in, const int* in_sizes, int n_in,
                              void* d_out, int out_size) {
    const int*   ids  = (const int*)d_in[0];
    const float* emb  = (const float*)d_in[1];
    const float* A    = (const float*)d_in[2];
    const float* Bm   = (const float*)d_in[3];
    const float* Cm   = (const float*)d_in[4];
    const float* Dm_  = (const float*)d_in[5];
    const float* Wp   = (const float*)d_in[6];
    const float* bp   = (const float*)d_in[7];
    float*       out  = (float*)d_out;

    prep_kernel<<<256, 256>>>(A, Bm, Cm);
    split_wp_kernel<<<(VOCAB * DM + 255) / 256, 256>>>(Wp);
    zero_bits_kernel<<<256, 256>>>();
    encode_kernel<<<(ROWS * DM + 255) / 256, 256>>>(ids, emb);

    ssm4_kernel<<<ROWS / 4, 256>>>(0, 0, 1, Dm_, 0);
    ssm4_kernel<<<ROWS / 4, 256>>>(1, 1, 0, Dm_, 0);
    ssm4_kernel<<<ROWS / 4, 256>>>(2, 0, 1, Dm_, 0);
    ssm4_kernel<<<ROWS / 4, 256>>>(3, 1, 0, Dm_, 1);   // fused count -> g_cntb

    cudaFuncSetAttribute(gemm_bf16_kernel,
                         cudaFuncAttributeMaxDynamicSharedMemorySize,
                         GSMEM_BYTES);
    gemm_bf16_kernel<<<dim3(ROWS / 128, VOCAB / 128), 256, GSMEM_BYTES>>>(bp, out);
}

// round 11
// speedup vs baseline: 1.1389x; 1.1389x over previous
#include <cuda_runtime.h>
#include <cuda_bf16.h>
#include <math.h>
#include <stdint.h>

#define TSTEPS  20
#define NLAYERS 4
#define DM      512
#define DS      128
#define ROWS    2048      // BATCH(4) * SEQ(512)
#define VOCAB   32000

// ---------------- scratch (device globals; no allocations allowed) ----------
__device__ uint32_t      g_bits[2][TSTEPS][ROWS][16];
__device__ float         g_AT[NLAYERS][DS * DS];      // AT[j*DS+i] = A[i][j]
__device__ float         g_BT[NLAYERS][DM * DS];      // BT[d*DS+i] = B[i][d]
__device__ float         g_CT[NLAYERS][DS * DM];      // CT[i*DM+d] = C[d][i]
__device__ __nv_bfloat16 g_cntb[ROWS * DM];           // exact integer spike counts
__device__ __nv_bfloat16 g_wph[(size_t)VOCAB * DM];   // bf16 hi of Wp
__device__ __nv_bfloat16 g_wpl[(size_t)VOCAB * DM];   // bf16 lo of Wp

// ---------------- weight transposes ----------------------------------------
__global__ void prep_kernel(const float* __restrict__ A,
                            const float* __restrict__ Bm,
                            const float* __restrict__ Cm) {
    int stride = gridDim.x * blockDim.x;
    int gid = blockIdx.x * blockDim.x + threadIdx.x;
    for (int idx = gid; idx < NLAYERS * DS * DS; idx += stride) {
        int l = idx / (DS * DS); int rm = idx % (DS * DS);
        int i = rm / DS, j = rm % DS;
        g_AT[l][j * DS + i] = A[idx];
    }
    for (int idx = gid; idx < NLAYERS * DS * DM; idx += stride) {
        int l = idx / (DS * DM); int rm = idx % (DS * DM);
        int i = rm / DM, d = rm % DM;
        g_BT[l][d * DS + i] = Bm[idx];
    }
    for (int idx = gid; idx < NLAYERS * DM * DS; idx += stride) {
        int l = idx / (DM * DS); int rm = idx % (DM * DS);
        int d = rm / DS, i = rm % DS;
        g_CT[l][i * DM + d] = Cm[idx];
    }
}

// ---------------- Wp two-term bf16 split ------------------------------------
__global__ void split_wp_kernel(const float* __restrict__ Wp) {
    long long i = (long long)blockIdx.x * blockDim.x + threadIdx.x;
    if (i >= (long long)VOCAB * DM) return;
    float w = Wp[i];
    __nv_bfloat16 h = __float2bfloat16(w);
    g_wph[i] = h;
    g_wpl[i] = __float2bfloat16(w - __bfloat162float(h));
}

__global__ void zero_bits_kernel() {
    int gid = blockIdx.x * blockDim.x + threadIdx.x;
    uint32_t* p = &g_bits[0][0][0][0];
    int n = TSTEPS * ROWS * 16;          // buffer 0 (encode's atomicOr target)
    for (int i = gid; i < n; i += gridDim.x * blockDim.x) p[i] = 0u;
}

// ---------------- temporal encoding (exact fp32 logistic, as validated) -----
__global__ void encode_kernel(const int* __restrict__ ids,
                              const float* __restrict__ emb) {
    int gid = blockIdx.x * blockDim.x + threadIdx.x;
    if (gid >= ROWS * DM) return;
    int r = gid >> 9, d = gid & (DM - 1);
    float x = emb[(long long)ids[r] * DM + d];
    float sgf = 1.0f / (1.0f + expf(-x));
    int t = (int)floorf(sgf * 19.0f);
    if (t < 0) t = 0;
    if (t > 19) t = 19;
    atomicOr(&g_bits[0][t][r][d >> 5], 1u << (d & 31));
}

// ---------------- one LIF-SSM layer (validated bit-exact R9 shape) ----------
// 1 row per 128-thread CTA. Ascending-order sparse sums, single accumulator
// per dot, separately rounded A/B dots (bit-exact vs reference trajectory).
// last!=0: spike counts accumulate in registers; writes g_cntb, not g_bits.
__global__ __launch_bounds__(128) void ssm_kernel(int layer, int inb, int outb,
                                                  const float* __restrict__ Dfull,
                                                  int last) {
    int r   = blockIdx.x;
    int tid = threadIdx.x;
    int lane = tid & 31, wp = tid >> 5;
    const float* __restrict__ AT = g_AT[layer];
    const float* __restrict__ BT = g_BT[layer];
    const float* __restrict__ CT = g_CT[layer];
    const float* __restrict__ Dv = Dfull + layer * DM;

    __shared__ uint32_t sh_x[16];
    __shared__ uint32_t sh_h[4];
    __shared__ int sh_xidx[512];
    __shared__ int sh_hidx[128];
    __shared__ int sh_nx, sh_nh;

    float v1 = 0.f;
    float v2[4] = {0.f, 0.f, 0.f, 0.f};
    float cnt[4] = {0.f, 0.f, 0.f, 0.f};
    if (tid == 0) { sh_nh = 0; sh_nx = 0; }

    for (int t = 0; t < TSTEPS; t++) {
        __syncthreads();
        if (tid < 16) sh_x[tid] = g_bits[inb][t][r][tid];
        __syncthreads();

        if (tid < 16) {
            uint32_t w = sh_x[tid];
            int c = __popc(w);
            int incl = c;
            #pragma unroll
            for (int off = 1; off < 16; off <<= 1) {
                int y = __shfl_up_sync(0xffffu, incl, off);
                if (tid >= off) incl += y;
            }
            int pos = incl - c;
            while (w) {
                int b = __ffs(w) - 1; w &= w - 1;
                sh_xidx[pos++] = ((tid << 5) + b) * DS;
            }
            if (tid == 15) sh_nx = incl;
        }
        __syncthreads();

        int nh = sh_nh, nx = sh_nx;
        float sa = 0.f;
        #pragma unroll 4
        for (int i = 0; i < nh; i++) sa += AT[sh_hidx[i] * DS + tid];
        float sb = 0.f;
        #pragma unroll 4
        for (int i = 0; i < nx; i++) sb += BT[sh_xidx[i] + tid];
        float u = sa + sb;

        v1 = v1 + (u - v1) * 0.5f;
        int s1 = (v1 - 1.0f) >= 0.f;
        uint32_t hb = __ballot_sync(0xffffffffu, s1);
        if (s1) v1 = 0.f;
        __syncthreads();
        if (lane == 0) sh_h[wp] = hb;
        __syncthreads();

        if (tid < 4) {
            uint32_t w = sh_h[tid];
            int c = __popc(w);
            int incl = c;
            #pragma unroll
            for (int off = 1; off < 4; off <<= 1) {
                int y = __shfl_up_sync(0xfu, incl, off);
                if (tid >= off) incl += y;
            }
            int pos = incl - c;
            while (w) {
                int b = __ffs(w) - 1; w &= w - 1;
                sh_hidx[pos++] = (tid << 5) + b;
            }
            if (tid == 3) sh_nh = incl;
        }
        __syncthreads();

        int nh2 = sh_nh;
        float sc0 = 0.f, sc1 = 0.f, sc2 = 0.f, sc3 = 0.f;
        #pragma unroll 2
        for (int i = 0; i < nh2; i++) {
            const float* crow = CT + sh_hidx[i] * DM + tid;
            sc0 += crow[0];
            sc1 += crow[128];
            sc2 += crow[256];
            sc3 += crow[384];
        }
        float sc[4] = {sc0, sc1, sc2, sc3};
        #pragma unroll
        for (int k = 0; k < 4; k++) {
            float u2 = sc[k];
            if ((sh_x[4 * k + wp] >> lane) & 1u) u2 = u2 + Dv[tid + 128 * k];
            v2[k] = v2[k] + (u2 - v2[k]) * 0.5f;
            int s2 = (v2[k] - 1.0f) >= 0.f;
            if (!last) {
                uint32_t ob = __ballot_sync(0xffffffffu, s2);
                if (lane == 0) g_bits[outb][t][r][4 * k + wp] = ob;
            } else {
                cnt[k] += s2 ? 1.0f : 0.0f;
            }
            if (s2) v2[k] = 0.f;
        }
    }

    if (last) {
        #pragma unroll
        for (int k = 0; k < 4; k++)
            g_cntb[(size_t)r * DM + tid + 128 * k] = __float2bfloat16(cnt[k]);
    }
}

// ============ logits GEMM: split-bf16 mma.sync + ldmatrix, 3-stage cp.async ==
#define SPAD   40                        // bf16 per smem row (80 B pitch)
#define KC     32                        // K per chunk
#define NCH    (DM / KC)                 // 16 chunks
#define ST     3                         // pipeline stages
#define MAT_B  (128 * SPAD * 2)          // 10240 B per matrix tile
#define STAGE_B (3 * MAT_B)              // A + Bh + Bl
#define GSMEM_BYTES (ST * STAGE_B)       // 92160

__device__ __forceinline__ void mma16816(float* d, const uint32_t* a, const uint32_t* b) {
    asm volatile(
        "mma.sync.aligned.m16n8k16.row.col.f32.bf16.bf16.f32 "
        "{%0,%1,%2,%3}, {%4,%5,%6,%7}, {%8,%9}, {%0,%1,%2,%3};"
        : "+f"(d[0]), "+f"(d[1]), "+f"(d[2]), "+f"(d[3])
        : "r"(a[0]), "r"(a[1]), "r"(a[2]), "r"(a[3]), "r"(b[0]), "r"(b[1]));
}
__device__ __forceinline__ void ldmx4(uint32_t* r, uint32_t a) {
    asm volatile("ldmatrix.sync.aligned.m8n8.x4.shared.b16 {%0,%1,%2,%3}, [%4];"
        : "=r"(r[0]), "=r"(r[1]), "=r"(r[2]), "=r"(r[3]) : "r"(a));
}
__device__ __forceinline__ void ldmx2(uint32_t* r, uint32_t a) {
    asm volatile("ldmatrix.sync.aligned.m8n8.x2.shared.b16 {%0,%1}, [%2];"
        : "=r"(r[0]), "=r"(r[1]) : "r"(a));
}
__device__ __forceinline__ void cpasync16(uint32_t dst, const void* src) {
    asm volatile("cp.async.ca.shared.global [%0], [%1], 16;" :: "r"(dst), "l"(src));
}
__device__ __forceinline__ uint32_t smem_u32(const void* p) {
    uint32_t a;
    asm("{ .reg .u64 t; cvta.to.shared.u64 t, %1; cvt.u32.u64 %0, t; }"
        : "=r"(a) : "l"(p));
    return a;
}

__global__ __launch_bounds__(256, 2) void gemm_bf16_kernel(const float* __restrict__ bp,
                                                           float* __restrict__ out) {
    extern __shared__ char smem[];
    uint32_t sbase = smem_u32(smem);

    int bm = blockIdx.x, bn = blockIdx.y;   // bm fastest -> Wp tile reused in L2
    int tid = threadIdx.x;
    int w   = tid >> 5;
    int wm  = w >> 2, wn = w & 3;           // 2 x 4 warps
    int lane = tid & 31;
    int g = lane >> 2, tig = lane & 3;

    const __nv_bfloat16* asrc = g_cntb + (size_t)(bm * 128) * DM;
    const __nv_bfloat16* hsrc = g_wph  + (size_t)(bn * 128) * DM;
    const __nv_bfloat16* lsrc = g_wpl  + (size_t)(bn * 128) * DM;

    int a_q = lane >> 3, a_r = lane & 7;
    uint32_t a_off = (uint32_t)(((wm * 64 + (a_q & 1) * 8 + a_r) * SPAD +
                                 (a_q >> 1) * 8) * 2);
    int b_r = lane & 7, b_q = (lane >> 3) & 1;
    uint32_t b_off = (uint32_t)(((wn * 32 + b_r) * SPAD + b_q * 8) * 2);

    int crow  = tid >> 1;
    int chalf = (tid & 1) * 32;

    auto issue_stage = [&](int s, int c) {
        uint32_t dbase = sbase + s * STAGE_B + crow * (SPAD * 2) + chalf;
        size_t goff = (size_t)crow * DM + c * KC + (chalf >> 1);
        cpasync16(dbase,                  asrc + goff);
        cpasync16(dbase + 16,             asrc + goff + 8);
        cpasync16(dbase + MAT_B,          hsrc + goff);
        cpasync16(dbase + MAT_B + 16,     hsrc + goff + 8);
        cpasync16(dbase + 2 * MAT_B,      lsrc + goff);
        cpasync16(dbase + 2 * MAT_B + 16, lsrc + goff + 8);
    };

    #pragma unroll
    for (int s = 0; s < ST - 1; s++) {
        issue_stage(s, s);
        asm volatile("cp.async.commit_group;" ::: "memory");
    }

    float acc[4][4][4];
    #pragma unroll
    for (int i = 0; i < 4; i++)
        #pragma unroll
        for (int j = 0; j < 4; j++)
            #pragma unroll
            for (int q = 0; q < 4; q++) acc[i][j][q] = 0.f;

    #pragma unroll 1
    for (int c = 0; c < NCH; c++) {
        if (c < NCH - 1) asm volatile("cp.async.wait_group 1;" ::: "memory");
        else             asm volatile("cp.async.wait_group 0;" ::: "memory");
        __syncthreads();

        if (c + 2 < NCH) {
            issue_stage((c + 2) % ST, c + 2);
            asm volatile("cp.async.commit_group;" ::: "memory");
        }

        uint32_t st = sbase + (c % ST) * STAGE_B;

        #pragma unroll
        for (int ks = 0; ks < KC / 16; ks++) {
            uint32_t kof = (uint32_t)(ks * 16 * 2);
            uint32_t afr[4][4];
            #pragma unroll
            for (int mf = 0; mf < 4; mf++)
                ldmx4(afr[mf], st + a_off + (uint32_t)(mf * 16 * SPAD * 2) + kof);
            #pragma unroll
            for (int nf = 0; nf < 4; nf++) {
                uint32_t bof = b_off + (uint32_t)(nf * 8 * SPAD * 2) + kof;
                uint32_t bh[2], bl[2];
                ldmx2(bh, st + MAT_B + bof);
                ldmx2(bl, st + 2 * MAT_B + bof);
                #pragma unroll
                for (int mf = 0; mf < 4; mf++) {
                    mma16816(acc[mf][nf], afr[mf], bh);
                    mma16816(acc[mf][nf], afr[mf], bl);
                }
            }
        }
        __syncthreads();
    }

    #pragma unroll
    for (int nf = 0; nf < 4; nf++) {
        int col = bn * 128 + wn * 32 + nf * 8 + 2 * tig;
        float2 bias = *(const float2*)(bp + col);
        #pragma unroll
        for (int mf = 0; mf < 4; mf++) {
            int row0 = bm * 128 + wm * 64 + mf * 16 + g;
            float2 o0, o1;
            o0.x = acc[mf][nf][0] * 0.05f + bias.x;
            o0.y = acc[mf][nf][1] * 0.05f + bias.y;
            o1.x = acc[mf][nf][2] * 0.05f + bias.x;
            o1.y = acc[mf][nf][3] * 0.05f + bias.y;
            *(float2*)(out + (size_t)row0 * VOCAB + col)       = o0;
            *(float2*)(out + (size_t)(row0 + 8) * VOCAB + col) = o1;
        }
    }
}

// ---------------- launch -----------------------------------------------------
// Launch order puts ssm0 at slot #4 so the profiler (which has been capturing
// launch #4 every round) finally reports the SSM kernel. split_wp is only
// needed before the GEMM, so it moves after the SSM chain.
extern "C" void kernel_launch(void* const* d_in, const int* in_sizes, int n_in,
                              void* d_out, int out_size) {
    const int*   ids  = (const int*)d_in[0];
    const float* emb  = (const float*)d_in[1];
    const float* A    = (const float*)d_in[2];
    const float* Bm   = (const float*)d_in[3];
    const float* Cm   = (const float*)d_in[4];
    const float* Dm_  = (const float*)d_in[5];
    const float* Wp   = (const float*)d_in[6];
    const float* bp   = (const float*)d_in[7];
    float*       out  = (float*)d_out;

    prep_kernel<<<256, 256>>>(A, Bm, Cm);
    zero_bits_kernel<<<256, 256>>>();
    encode_kernel<<<(ROWS * DM + 255) / 256, 256>>>(ids, emb);

    ssm_kernel<<<ROWS, 128>>>(0, 0, 1, Dm_, 0);   // launch #4 -> profiled
    ssm_kernel<<<ROWS, 128>>>(1, 1, 0, Dm_, 0);
    ssm_kernel<<<ROWS, 128>>>(2, 0, 1, Dm_, 0);
    ssm_kernel<<<ROWS, 128>>>(3, 1, 0, Dm_, 1);   // fused count -> g_cntb

    split_wp_kernel<<<(VOCAB * DM + 255) / 256, 256>>>(Wp);

    cudaFuncSetAttribute(gemm_bf16_kernel,
                         cudaFuncAttributeMaxDynamicSharedMemorySize,
                         GSMEM_BYTES);
    gemm_bf16_kernel<<<dim3(ROWS / 128, VOCAB / 128), 256, GSMEM_BYTES>>>(bp, out);
}